// round 2
// baseline (speedup 1.0000x reference)
#include <cuda_runtime.h>
#include <cstdint>

#define NNODES 16384
#define NEDGES 262144
#define F_IN   256
#define F_H    128
#define F_Z    64

// ---------------- scratch (static device memory; no allocation) ----------------
__device__ __align__(256) float g_deg_src[NNODES];
__device__ __align__(256) float g_deg_dst[NNODES];
__device__ __align__(256) float g_cs[NNODES];
__device__ __align__(256) float g_cd[NNODES];
__device__ __align__(256) float g_hpre[NNODES * F_H];   // (x*c_src)@W1
__device__ __align__(256) float g_agg1[NNODES * F_H];   // scatter of hpre
__device__ __align__(256) float g_hs  [NNODES * F_H];   // relu(..)*c_src
__device__ __align__(256) float g_agg2[NNODES * F_H];   // scatter of hs

// ---------------- helpers ----------------
__device__ __forceinline__ unsigned long long pk2(float lo, float hi) {
    unsigned long long r;
    asm("mov.b64 %0, {%1, %2};" : "=l"(r) : "f"(lo), "f"(hi));
    return r;
}
__device__ __forceinline__ void fma2(unsigned long long& d, unsigned long long a, unsigned long long b) {
    asm("fma.rn.f32x2 %0, %1, %2, %0;" : "+l"(d) : "l"(a), "l"(b));
}
__device__ __forceinline__ float2 upk2(unsigned long long v) {
    float2 r;
    asm("mov.b64 {%0, %1}, %2;" : "=f"(r.x), "=f"(r.y) : "l"(v));
    return r;
}
__device__ __forceinline__ float sigm(float x) {
    return __fdividef(1.0f, 1.0f + __expf(-x));
}
__device__ __forceinline__ void red4(float* p, float4 v) {
    asm volatile("red.global.add.v4.f32 [%0], {%1,%2,%3,%4};"
                 :: "l"(p), "f"(v.x), "f"(v.y), "f"(v.z), "f"(v.w) : "memory");
}

// ---------------- K0: zero scratch (must re-zero every replay) ----------------
__global__ void k_zero() {
    int idx = blockIdx.x * blockDim.x + threadIdx.x;
    int stride = gridDim.x * blockDim.x;
    for (int i = idx; i < NNODES * F_H; i += stride) { g_agg1[i] = 0.f; g_agg2[i] = 0.f; }
    for (int i = idx; i < NNODES; i += stride) { g_deg_src[i] = 0.f; g_deg_dst[i] = 0.f; }
}

// ---------------- K1: degrees ----------------
__global__ void k_degree(const int* __restrict__ es, const int* __restrict__ ed) {
    int i = blockIdx.x * blockDim.x + threadIdx.x;
    if (i < NEDGES) {
        atomicAdd(&g_deg_src[es[i]], 1.0f);
        atomicAdd(&g_deg_dst[ed[i]], 1.0f);
    }
}

// ---------------- K2: norms c = deg^-1/2 (0 if deg==0) ----------------
__global__ void k_norm() {
    int i = blockIdx.x * blockDim.x + threadIdx.x;
    if (i < NNODES) {
        float a = g_deg_src[i], b = g_deg_dst[i];
        g_cs[i] = (a > 0.f) ? rsqrtf(a) : 0.f;
        g_cd[i] = (b > 0.f) ? rsqrtf(b) : 0.f;
    }
}

// ---------------- K3: GEMM1  h_pre = (x * c_src) @ W1   [16384,256]x[256,128] ----------------
// block: 256 threads (16x16 logical), tile 64(M) x 128(N), K-chunks of 32
__global__ __launch_bounds__(256) void k_gemm1(const float* __restrict__ X, const float* __restrict__ W1) {
    __shared__ float As[32 * 68];    // transposed: As[k][row]
    __shared__ float Bs[32 * 128];   // Bs[k][j]
    int tid = threadIdx.x;
    int tx = tid & 15, ty = tid >> 4;
    int bi = blockIdx.x;
    int row0 = bi * 64;

    float acc[4][8];
#pragma unroll
    for (int i = 0; i < 4; i++)
#pragma unroll
        for (int j = 0; j < 8; j++) acc[i][j] = 0.f;

    for (int k0 = 0; k0 < F_IN; k0 += 32) {
        // load A tile (64 rows x 32 k) scaled by c_src, transposed store
#pragma unroll
        for (int r = 0; r < 2; r++) {
            int idx = tid + 256 * r;            // 512 float4s
            int row = idx >> 3, kq = idx & 7;
            float c = g_cs[row0 + row];
            float4 v = *(const float4*)(X + (size_t)(row0 + row) * F_IN + k0 + kq * 4);
            As[(kq * 4 + 0) * 68 + row] = v.x * c;
            As[(kq * 4 + 1) * 68 + row] = v.y * c;
            As[(kq * 4 + 2) * 68 + row] = v.z * c;
            As[(kq * 4 + 3) * 68 + row] = v.w * c;
        }
        // load B tile (32 k x 128 j)
#pragma unroll
        for (int r = 0; r < 4; r++) {
            int idx = tid + 256 * r;            // 1024 float4s
            int kk = idx >> 5, jq = idx & 31;
            *(float4*)(Bs + kk * 128 + jq * 4) =
                *(const float4*)(W1 + (size_t)(k0 + kk) * F_H + jq * 4);
        }
        __syncthreads();
#pragma unroll 8
        for (int k = 0; k < 32; k++) {
            float4 a = *(const float4*)(As + k * 68 + ty * 4);
            float4 b0 = *(const float4*)(Bs + k * 128 + tx * 8);
            float4 b1 = *(const float4*)(Bs + k * 128 + tx * 8 + 4);
            float av[4] = {a.x, a.y, a.z, a.w};
            float bv[8] = {b0.x, b0.y, b0.z, b0.w, b1.x, b1.y, b1.z, b1.w};
#pragma unroll
            for (int i = 0; i < 4; i++)
#pragma unroll
                for (int j = 0; j < 8; j++) acc[i][j] = fmaf(av[i], bv[j], acc[i][j]);
        }
        __syncthreads();
    }
#pragma unroll
    for (int i = 0; i < 4; i++) {
        float* p = g_hpre + (size_t)(row0 + ty * 4 + i) * F_H + tx * 8;
        *(float4*)(p)     = make_float4(acc[i][0], acc[i][1], acc[i][2], acc[i][3]);
        *(float4*)(p + 4) = make_float4(acc[i][4], acc[i][5], acc[i][6], acc[i][7]);
    }
}

// ---------------- scatter: one warp per edge, 128 floats = 32 lanes x float4 ----------------
__device__ __forceinline__ void scatter_body(const float* __restrict__ feat, float* __restrict__ agg,
                                             const int* __restrict__ es, const int* __restrict__ ed) {
    int g = blockIdx.x * blockDim.x + threadIdx.x;
    int e = g >> 5;
    int lane = g & 31;
    if (e >= NEDGES) return;
    int s = __ldg(es + e), d = __ldg(ed + e);
    float4 v = *(const float4*)(feat + (size_t)s * F_H + lane * 4);
    red4(agg + (size_t)d * F_H + lane * 4, v);
}
__global__ void k_scatter1(const int* __restrict__ es, const int* __restrict__ ed) {
    scatter_body(g_hpre, g_agg1, es, ed);
}
__global__ void k_scatter2(const int* __restrict__ es, const int* __restrict__ ed) {
    scatter_body(g_hs, g_agg2, es, ed);
}

// ---------------- K5: h_src = relu(agg1*c_dst + b1) * c_src ----------------
__global__ void k_act(const float* __restrict__ b1) {
    int unit = blockIdx.x * blockDim.x + threadIdx.x;     // N*128/4 units
    if (unit >= NNODES * F_H / 4) return;
    int node = unit >> 5;
    int q = unit & 31;
    float cd = g_cd[node], cs = g_cs[node];
    float4 a = *(const float4*)(g_agg1 + (size_t)unit * 4);
    float4 b = *(const float4*)(b1 + q * 4);
    float4 h;
    h.x = fmaxf(fmaf(a.x, cd, b.x), 0.f) * cs;
    h.y = fmaxf(fmaf(a.y, cd, b.y), 0.f) * cs;
    h.z = fmaxf(fmaf(a.z, cd, b.z), 0.f) * cs;
    h.w = fmaxf(fmaf(a.w, cd, b.w), 0.f) * cs;
    *(float4*)(g_hs + (size_t)unit * 4) = h;
}

// ---------------- K7: fused GEMM2  mean/log_std -> z ----------------
// z = (agg2@Wm)*c_dst + bm + noise * exp((agg2@Ws)*c_dst + bs)
// tile 64 nodes x 64 dims, K=128 in 4 chunks of 32. micro 4x4 with dual accumulators.
__global__ __launch_bounds__(256) void k_gemm2(const float* __restrict__ Wm, const float* __restrict__ bm,
                                               const float* __restrict__ Ws, const float* __restrict__ bs,
                                               const float* __restrict__ noise, float* __restrict__ zb) {
    __shared__ float As[32 * 68];   // transposed agg2 chunk
    __shared__ float Bm[32 * 64];
    __shared__ float Bv[32 * 64];
    int tid = threadIdx.x;
    int tx = tid & 15, ty = tid >> 4;
    int bi = blockIdx.x;
    int row0 = bi * 64;

    float am[4][4], av[4][4];
#pragma unroll
    for (int i = 0; i < 4; i++)
#pragma unroll
        for (int j = 0; j < 4; j++) { am[i][j] = 0.f; av[i][j] = 0.f; }

    for (int k0 = 0; k0 < F_H; k0 += 32) {
#pragma unroll
        for (int r = 0; r < 2; r++) {
            int idx = tid + 256 * r;           // 512 float4s (64 rows x 8 quads)
            int row = idx >> 3, kq = idx & 7;
            float4 v = *(const float4*)(g_agg2 + (size_t)(row0 + row) * F_H + k0 + kq * 4);
            As[(kq * 4 + 0) * 68 + row] = v.x;
            As[(kq * 4 + 1) * 68 + row] = v.y;
            As[(kq * 4 + 2) * 68 + row] = v.z;
            As[(kq * 4 + 3) * 68 + row] = v.w;
        }
        // B tiles: 32 k-rows x 64 cols each = 512 float4 per matrix.
        // All 256 threads load 2 float4 per matrix (fixes round-1 bug where
        // k-rows 16..31 were never written).
#pragma unroll
        for (int r = 0; r < 2; r++) {
            int idx = tid + 256 * r;           // 0..511
            int kk = idx >> 4;                 // 0..31
            int jq = idx & 15;                 // 0..15
            *(float4*)(Bm + kk * 64 + jq * 4) =
                *(const float4*)(Wm + (size_t)(k0 + kk) * F_Z + jq * 4);
            *(float4*)(Bv + kk * 64 + jq * 4) =
                *(const float4*)(Ws + (size_t)(k0 + kk) * F_Z + jq * 4);
        }
        __syncthreads();
#pragma unroll 8
        for (int k = 0; k < 32; k++) {
            float4 a = *(const float4*)(As + k * 68 + ty * 4);
            float4 m4 = *(const float4*)(Bm + k * 64 + tx * 4);
            float4 v4 = *(const float4*)(Bv + k * 64 + tx * 4);
            float avv[4] = {a.x, a.y, a.z, a.w};
            float mv[4] = {m4.x, m4.y, m4.z, m4.w};
            float vv[4] = {v4.x, v4.y, v4.z, v4.w};
#pragma unroll
            for (int i = 0; i < 4; i++)
#pragma unroll
                for (int j = 0; j < 4; j++) {
                    am[i][j] = fmaf(avv[i], mv[j], am[i][j]);
                    av[i][j] = fmaf(avv[i], vv[j], av[i][j]);
                }
        }
        __syncthreads();
    }
    float4 bmv = *(const float4*)(bm + tx * 4);
    float4 bsv = *(const float4*)(bs + tx * 4);
#pragma unroll
    for (int i = 0; i < 4; i++) {
        int node = row0 + ty * 4 + i;
        float cd = g_cd[node];
        float4 nz = *(const float4*)(noise + (size_t)node * F_Z + tx * 4);
        float4 z;
        z.x = fmaf(am[i][0], cd, bmv.x) + nz.x * __expf(fmaf(av[i][0], cd, bsv.x));
        z.y = fmaf(am[i][1], cd, bmv.y) + nz.y * __expf(fmaf(av[i][1], cd, bsv.y));
        z.z = fmaf(am[i][2], cd, bmv.z) + nz.z * __expf(fmaf(av[i][2], cd, bsv.z));
        z.w = fmaf(am[i][3], cd, bmv.w) + nz.w * __expf(fmaf(av[i][3], cd, bsv.w));
        *(float4*)(zb + (size_t)node * F_Z + tx * 4) = z;
    }
}

// ---------------- K8: pre = sigmoid(Z Z^T), symmetric, f32x2 packed FMA ----------------
// grid (256,256); only bj>=bi computes; 64x64 tile, K=64 fully resident.
__global__ __launch_bounds__(256) void k_biggemm(const float* __restrict__ Z, float* __restrict__ out) {
    int bi = blockIdx.y, bj = blockIdx.x;
    if (bj < bi) return;
    __shared__ float sm[2 * 64 * 68];
    float* As = sm;
    float* Bs = sm + 64 * 68;
    int tid = threadIdx.x;
    int tx = tid & 15, ty = tid >> 4;

    // load both tiles transposed: As[k][i], Bs[k][j]
#pragma unroll
    for (int r = 0; r < 4; r++) {
        int idx = tid + 256 * r;               // 1024 float4s per tile
        int row = idx >> 4, kq = idx & 15;
        float4 va = *(const float4*)(Z + (size_t)(bi * 64 + row) * F_Z + kq * 4);
        As[(kq * 4 + 0) * 68 + row] = va.x;
        As[(kq * 4 + 1) * 68 + row] = va.y;
        As[(kq * 4 + 2) * 68 + row] = va.z;
        As[(kq * 4 + 3) * 68 + row] = va.w;
        float4 vb = *(const float4*)(Z + (size_t)(bj * 64 + row) * F_Z + kq * 4);
        Bs[(kq * 4 + 0) * 68 + row] = vb.x;
        Bs[(kq * 4 + 1) * 68 + row] = vb.y;
        Bs[(kq * 4 + 2) * 68 + row] = vb.z;
        Bs[(kq * 4 + 3) * 68 + row] = vb.w;
    }
    __syncthreads();

    unsigned long long acc[4][2];
#pragma unroll
    for (int i = 0; i < 4; i++) { acc[i][0] = 0ull; acc[i][1] = 0ull; }

#pragma unroll 16
    for (int k = 0; k < 64; k++) {
        float4 a = *(const float4*)(As + k * 68 + ty * 4);
        ulonglong2 b = *(const ulonglong2*)(Bs + k * 68 + tx * 4);
        unsigned long long a0 = pk2(a.x, a.x);
        unsigned long long a1 = pk2(a.y, a.y);
        unsigned long long a2 = pk2(a.z, a.z);
        unsigned long long a3 = pk2(a.w, a.w);
        fma2(acc[0][0], a0, b.x); fma2(acc[0][1], a0, b.y);
        fma2(acc[1][0], a1, b.x); fma2(acc[1][1], a1, b.y);
        fma2(acc[2][0], a2, b.x); fma2(acc[2][1], a2, b.y);
        fma2(acc[3][0], a3, b.x); fma2(acc[3][1], a3, b.y);
    }

    float s[4][4];
#pragma unroll
    for (int i = 0; i < 4; i++) {
        float2 p0 = upk2(acc[i][0]);
        float2 p1 = upk2(acc[i][1]);
        s[i][0] = sigm(p0.x); s[i][1] = sigm(p0.y);
        s[i][2] = sigm(p1.x); s[i][3] = sigm(p1.y);
    }

    const size_t NN = (size_t)NNODES;
    int row0 = bi * 64 + ty * 4, col0 = bj * 64 + tx * 4;
#pragma unroll
    for (int i = 0; i < 4; i++)
        *(float4*)(out + (size_t)(row0 + i) * NN + col0) =
            make_float4(s[i][0], s[i][1], s[i][2], s[i][3]);

    if (bi != bj) {
        __syncthreads();                       // done reading As/Bs
        float* Ts = sm;                        // 64 x 65 staging
#pragma unroll
        for (int i = 0; i < 4; i++)
#pragma unroll
            for (int j = 0; j < 4; j++)
                Ts[(tx * 4 + j) * 65 + (ty * 4 + i)] = s[i][j];
        __syncthreads();
#pragma unroll
        for (int i = 0; i < 4; i++) {
            int rr = bj * 64 + ty * 4 + i;
            int cc = bi * 64 + tx * 4;
            float4 w = make_float4(Ts[(ty * 4 + i) * 65 + tx * 4 + 0],
                                   Ts[(ty * 4 + i) * 65 + tx * 4 + 1],
                                   Ts[(ty * 4 + i) * 65 + tx * 4 + 2],
                                   Ts[(ty * 4 + i) * 65 + tx * 4 + 3]);
            *(float4*)(out + (size_t)rr * NN + cc) = w;
        }
    }
}

// ---------------- launch ----------------
extern "C" void kernel_launch(void* const* d_in, const int* in_sizes, int n_in,
                              void* d_out, int out_size) {
    const float* features = (const float*)d_in[0];
    const float* W1 = (const float*)d_in[1];
    const float* b1 = (const float*)d_in[2];
    const float* Wm = (const float*)d_in[3];
    const float* bm = (const float*)d_in[4];
    const float* Ws = (const float*)d_in[5];
    const float* bs = (const float*)d_in[6];
    const float* noise = (const float*)d_in[7];
    const int* es = (const int*)d_in[8];
    const int* ed = (const int*)d_in[9];

    float* out = (float*)d_out;
    float* zb = out + (size_t)NNODES * NNODES;   // z lives at tail of output

    k_zero<<<512, 256>>>();
    k_degree<<<NEDGES / 256, 256>>>(es, ed);
    k_norm<<<NNODES / 256, 256>>>();
    k_gemm1<<<NNODES / 64, 256>>>(features, W1);
    k_scatter1<<<(NEDGES * 32) / 256, 256>>>(es, ed);
    k_act<<<(NNODES * F_H / 4) / 256, 256>>>(b1);
    k_scatter2<<<(NEDGES * 32) / 256, 256>>>(es, ed);
    k_gemm2<<<NNODES / 64, 256>>>(Wm, bm, Ws, bs, noise, zb);
    dim3 grid(NNODES / 64, NNODES / 64);
    k_biggemm<<<grid, 256>>>(zb, out);
}

// round 5
// speedup vs baseline: 1.1052x; 1.1052x over previous
#include <cuda_runtime.h>
#include <cstdint>

#define NNODES 16384
#define NEDGES 262144
#define F_IN   256
#define F_H    128
#define F_Z    64

// ---------------- scratch (static device memory; no allocation) ----------------
__device__ __align__(256) int   g_degi_src[NNODES];
__device__ __align__(256) int   g_degi_dst[NNODES];
__device__ __align__(256) int   g_rowptr[NNODES + 1];
__device__ __align__(256) int   g_cursor[NNODES];
__device__ __align__(256) int   g_eidx[NEDGES];
__device__ __align__(256) float g_cs[NNODES];
__device__ __align__(256) float g_cd[NNODES];
__device__ __align__(256) float g_hpre[NNODES * F_H];   // (x*c_src)@W1
__device__ __align__(256) float g_hs  [NNODES * F_H];   // relu(conv1)*c_src
__device__ __align__(256) float g_agg2[NNODES * F_H];   // CSR-gather of g_hs

// ---------------- helpers ----------------
__device__ __forceinline__ unsigned long long pk2(float lo, float hi) {
    unsigned long long r;
    asm("mov.b64 %0, {%1, %2};" : "=l"(r) : "f"(lo), "f"(hi));
    return r;
}
__device__ __forceinline__ void fma2(unsigned long long& d, unsigned long long a, unsigned long long b) {
    asm("fma.rn.f32x2 %0, %1, %2, %0;" : "+l"(d) : "l"(a), "l"(b));
}
__device__ __forceinline__ float2 upk2(unsigned long long v) {
    float2 r;
    asm("mov.b64 {%0, %1}, %2;" : "=f"(r.x), "=f"(r.y) : "l"(v));
    return r;
}
__device__ __forceinline__ float sigm(float x) {
    return __fdividef(1.0f, 1.0f + __expf(-x));
}

// ---------------- K0: zero small int scratch (re-zeroed every replay) ----------------
__global__ void k_zero() {
    int i = blockIdx.x * blockDim.x + threadIdx.x;   // 16384 threads
    g_degi_src[i] = 0;
    g_degi_dst[i] = 0;
    g_cursor[i] = 0;
}

// ---------------- K1: integer degrees ----------------
__global__ void k_degree(const int* __restrict__ es, const int* __restrict__ ed) {
    int i = blockIdx.x * blockDim.x + threadIdx.x;
    if (i < NEDGES) {
        atomicAdd(&g_degi_src[es[i]], 1);
        atomicAdd(&g_degi_dst[ed[i]], 1);
    }
}

// ---------------- K2: exclusive scan of in-degrees -> rowptr, plus norms ----------------
// single block, 1024 threads x 16 elements
__global__ __launch_bounds__(1024) void k_scan() {
    __shared__ int sm[1024];
    int tid = threadIdx.x;
    int base = tid * 16;
    int loc[16];
    int run = 0;
#pragma unroll
    for (int j = 0; j < 16; j++) { loc[j] = run; run += g_degi_dst[base + j]; }
    sm[tid] = run;
    __syncthreads();
    for (int off = 1; off < 1024; off <<= 1) {
        int v = (tid >= off) ? sm[tid - off] : 0;
        __syncthreads();
        sm[tid] += v;
        __syncthreads();
    }
    int excl = sm[tid] - run;
#pragma unroll
    for (int j = 0; j < 16; j++) g_rowptr[base + j] = excl + loc[j];
    if (tid == 1023) g_rowptr[NNODES] = excl + run;   // == NEDGES
    // norms
#pragma unroll
    for (int j = 0; j < 16; j++) {
        int i = base + j;
        int ds = g_degi_src[i], dd = g_degi_dst[i];
        g_cs[i] = ds > 0 ? rsqrtf((float)ds) : 0.f;
        g_cd[i] = dd > 0 ? rsqrtf((float)dd) : 0.f;
    }
}

// ---------------- K3: CSR fill (edge src ids bucketed by dst) ----------------
__global__ void k_fill(const int* __restrict__ es, const int* __restrict__ ed) {
    int e = blockIdx.x * blockDim.x + threadIdx.x;
    if (e < NEDGES) {
        int d = ed[e];
        int pos = g_rowptr[d] + atomicAdd(&g_cursor[d], 1);
        g_eidx[pos] = es[e];
    }
}

// ---------------- K4: GEMM1  h_pre = (x * c_src) @ W1   [16384,256]x[256,128] ----------------
__global__ __launch_bounds__(256) void k_gemm1(const float* __restrict__ X, const float* __restrict__ W1) {
    __shared__ float As[32 * 68];    // transposed: As[k][row]
    __shared__ float Bs[32 * 128];   // Bs[k][j]
    int tid = threadIdx.x;
    int tx = tid & 15, ty = tid >> 4;
    int bi = blockIdx.x;
    int row0 = bi * 64;

    float acc[4][8];
#pragma unroll
    for (int i = 0; i < 4; i++)
#pragma unroll
        for (int j = 0; j < 8; j++) acc[i][j] = 0.f;

    for (int k0 = 0; k0 < F_IN; k0 += 32) {
#pragma unroll
        for (int r = 0; r < 2; r++) {
            int idx = tid + 256 * r;            // 512 float4s
            int row = idx >> 3, kq = idx & 7;
            float c = g_cs[row0 + row];
            float4 v = *(const float4*)(X + (size_t)(row0 + row) * F_IN + k0 + kq * 4);
            As[(kq * 4 + 0) * 68 + row] = v.x * c;
            As[(kq * 4 + 1) * 68 + row] = v.y * c;
            As[(kq * 4 + 2) * 68 + row] = v.z * c;
            As[(kq * 4 + 3) * 68 + row] = v.w * c;
        }
#pragma unroll
        for (int r = 0; r < 4; r++) {
            int idx = tid + 256 * r;            // 1024 float4s
            int kk = idx >> 5, jq = idx & 31;
            *(float4*)(Bs + kk * 128 + jq * 4) =
                *(const float4*)(W1 + (size_t)(k0 + kk) * F_H + jq * 4);
        }
        __syncthreads();
#pragma unroll 8
        for (int k = 0; k < 32; k++) {
            float4 a = *(const float4*)(As + k * 68 + ty * 4);
            float4 b0 = *(const float4*)(Bs + k * 128 + tx * 8);
            float4 b1 = *(const float4*)(Bs + k * 128 + tx * 8 + 4);
            float av[4] = {a.x, a.y, a.z, a.w};
            float bv[8] = {b0.x, b0.y, b0.z, b0.w, b1.x, b1.y, b1.z, b1.w};
#pragma unroll
            for (int i = 0; i < 4; i++)
#pragma unroll
                for (int j = 0; j < 8; j++) acc[i][j] = fmaf(av[i], bv[j], acc[i][j]);
        }
        __syncthreads();
    }
#pragma unroll
    for (int i = 0; i < 4; i++) {
        float* p = g_hpre + (size_t)(row0 + ty * 4 + i) * F_H + tx * 8;
        *(float4*)(p)     = make_float4(acc[i][0], acc[i][1], acc[i][2], acc[i][3]);
        *(float4*)(p + 4) = make_float4(acc[i][4], acc[i][5], acc[i][6], acc[i][7]);
    }
}

// ---------------- K5/K6: CSR gather-aggregate, one warp per dst node ----------------
// agg1 fuses the activation: h_s = relu(sum*cd + b1) * cs
__global__ __launch_bounds__(256) void k_agg1(const float* __restrict__ b1) {
    int gid = blockIdx.x * blockDim.x + threadIdx.x;
    int node = gid >> 5;
    int lane = gid & 31;
    int beg = g_rowptr[node], end = g_rowptr[node + 1];
    float4 a0 = make_float4(0, 0, 0, 0), a1 = make_float4(0, 0, 0, 0);
    int i = beg;
    for (; i + 2 <= end; i += 2) {
        int s0 = __ldg(g_eidx + i), s1 = __ldg(g_eidx + i + 1);
        float4 v0 = *(const float4*)(g_hpre + (size_t)s0 * F_H + lane * 4);
        float4 v1 = *(const float4*)(g_hpre + (size_t)s1 * F_H + lane * 4);
        a0.x += v0.x; a0.y += v0.y; a0.z += v0.z; a0.w += v0.w;
        a1.x += v1.x; a1.y += v1.y; a1.z += v1.z; a1.w += v1.w;
    }
    if (i < end) {
        int s0 = __ldg(g_eidx + i);
        float4 v0 = *(const float4*)(g_hpre + (size_t)s0 * F_H + lane * 4);
        a0.x += v0.x; a0.y += v0.y; a0.z += v0.z; a0.w += v0.w;
    }
    float cd = g_cd[node], cs = g_cs[node];
    float4 b = *(const float4*)(b1 + lane * 4);
    float4 h;
    h.x = fmaxf(fmaf(a0.x + a1.x, cd, b.x), 0.f) * cs;
    h.y = fmaxf(fmaf(a0.y + a1.y, cd, b.y), 0.f) * cs;
    h.z = fmaxf(fmaf(a0.z + a1.z, cd, b.z), 0.f) * cs;
    h.w = fmaxf(fmaf(a0.w + a1.w, cd, b.w), 0.f) * cs;
    *(float4*)(g_hs + (size_t)node * F_H + lane * 4) = h;
}

__global__ __launch_bounds__(256) void k_agg2() {
    int gid = blockIdx.x * blockDim.x + threadIdx.x;
    int node = gid >> 5;
    int lane = gid & 31;
    int beg = g_rowptr[node], end = g_rowptr[node + 1];
    float4 a0 = make_float4(0, 0, 0, 0), a1 = make_float4(0, 0, 0, 0);
    int i = beg;
    for (; i + 2 <= end; i += 2) {
        int s0 = __ldg(g_eidx + i), s1 = __ldg(g_eidx + i + 1);
        float4 v0 = *(const float4*)(g_hs + (size_t)s0 * F_H + lane * 4);
        float4 v1 = *(const float4*)(g_hs + (size_t)s1 * F_H + lane * 4);
        a0.x += v0.x; a0.y += v0.y; a0.z += v0.z; a0.w += v0.w;
        a1.x += v1.x; a1.y += v1.y; a1.z += v1.z; a1.w += v1.w;
    }
    if (i < end) {
        int s0 = __ldg(g_eidx + i);
        float4 v0 = *(const float4*)(g_hs + (size_t)s0 * F_H + lane * 4);
        a0.x += v0.x; a0.y += v0.y; a0.z += v0.z; a0.w += v0.w;
    }
    float4 r;
    r.x = a0.x + a1.x; r.y = a0.y + a1.y; r.z = a0.z + a1.z; r.w = a0.w + a1.w;
    *(float4*)(g_agg2 + (size_t)node * F_H + lane * 4) = r;
}

// ---------------- K7: fused GEMM2  mean/log_std -> z ----------------
__global__ __launch_bounds__(256) void k_gemm2(const float* __restrict__ Wm, const float* __restrict__ bm,
                                               const float* __restrict__ Ws, const float* __restrict__ bs,
                                               const float* __restrict__ noise, float* __restrict__ zb) {
    __shared__ float As[32 * 68];   // transposed agg2 chunk
    __shared__ float Bm[32 * 64];
    __shared__ float Bv[32 * 64];
    int tid = threadIdx.x;
    int tx = tid & 15, ty = tid >> 4;
    int bi = blockIdx.x;
    int row0 = bi * 64;

    float am[4][4], av[4][4];
#pragma unroll
    for (int i = 0; i < 4; i++)
#pragma unroll
        for (int j = 0; j < 4; j++) { am[i][j] = 0.f; av[i][j] = 0.f; }

    for (int k0 = 0; k0 < F_H; k0 += 32) {
#pragma unroll
        for (int r = 0; r < 2; r++) {
            int idx = tid + 256 * r;           // 512 float4s (64 rows x 8 quads)
            int row = idx >> 3, kq = idx & 7;
            float4 v = *(const float4*)(g_agg2 + (size_t)(row0 + row) * F_H + k0 + kq * 4);
            As[(kq * 4 + 0) * 68 + row] = v.x;
            As[(kq * 4 + 1) * 68 + row] = v.y;
            As[(kq * 4 + 2) * 68 + row] = v.z;
            As[(kq * 4 + 3) * 68 + row] = v.w;
        }
#pragma unroll
        for (int r = 0; r < 2; r++) {
            int idx = tid + 256 * r;           // 0..511
            int kk = idx >> 4;                 // 0..31
            int jq = idx & 15;                 // 0..15
            *(float4*)(Bm + kk * 64 + jq * 4) =
                *(const float4*)(Wm + (size_t)(k0 + kk) * F_Z + jq * 4);
            *(float4*)(Bv + kk * 64 + jq * 4) =
                *(const float4*)(Ws + (size_t)(k0 + kk) * F_Z + jq * 4);
        }
        __syncthreads();
#pragma unroll 8
        for (int k = 0; k < 32; k++) {
            float4 a = *(const float4*)(As + k * 68 + ty * 4);
            float4 m4 = *(const float4*)(Bm + k * 64 + tx * 4);
            float4 v4 = *(const float4*)(Bv + k * 64 + tx * 4);
            float avv[4] = {a.x, a.y, a.z, a.w};
            float mv[4] = {m4.x, m4.y, m4.z, m4.w};
            float vv[4] = {v4.x, v4.y, v4.z, v4.w};
#pragma unroll
            for (int i = 0; i < 4; i++)
#pragma unroll
                for (int j = 0; j < 4; j++) {
                    am[i][j] = fmaf(avv[i], mv[j], am[i][j]);
                    av[i][j] = fmaf(avv[i], vv[j], av[i][j]);
                }
        }
        __syncthreads();
    }
    float4 bmv = *(const float4*)(bm + tx * 4);
    float4 bsv = *(const float4*)(bs + tx * 4);
#pragma unroll
    for (int i = 0; i < 4; i++) {
        int node = row0 + ty * 4 + i;
        float cd = g_cd[node];
        float4 nz = *(const float4*)(noise + (size_t)node * F_Z + tx * 4);
        float4 z;
        z.x = fmaf(am[i][0], cd, bmv.x) + nz.x * __expf(fmaf(av[i][0], cd, bsv.x));
        z.y = fmaf(am[i][1], cd, bmv.y) + nz.y * __expf(fmaf(av[i][1], cd, bsv.y));
        z.z = fmaf(am[i][2], cd, bmv.z) + nz.z * __expf(fmaf(av[i][2], cd, bsv.z));
        z.w = fmaf(am[i][3], cd, bmv.w) + nz.w * __expf(fmaf(av[i][3], cd, bsv.w));
        *(float4*)(zb + (size_t)node * F_Z + tx * 4) = z;
    }
}

// ---------------- K8: pre = sigmoid(Z Z^T), symmetric, 128x128 tile, f32x2 ----------------
// 256 threads, 8x8 outputs/thread, K=64 fully SMEM-resident. Dynamic smem 67584B.
__global__ __launch_bounds__(256) void k_biggemm(const float* __restrict__ Z, float* __restrict__ out) {
    int bi = blockIdx.y, bj = blockIdx.x;
    if (bj < bi) return;
    extern __shared__ float sm[];              // 2 * 64 * 132 floats
    float* As = sm;                            // As[k*132 + i]
    float* Bs = sm + 64 * 132;                 // Bs[k*132 + j]
    int tid = threadIdx.x;
    int tx = tid & 15, ty = tid >> 4;

    // load both 128x64 tiles transposed into SMEM
#pragma unroll
    for (int r = 0; r < 8; r++) {
        int idx = tid + 256 * r;               // 0..2047
        int row = idx >> 4, kq = idx & 15;
        float4 va = *(const float4*)(Z + (size_t)(bi * 128 + row) * F_Z + kq * 4);
        As[(kq * 4 + 0) * 132 + row] = va.x;
        As[(kq * 4 + 1) * 132 + row] = va.y;
        As[(kq * 4 + 2) * 132 + row] = va.z;
        As[(kq * 4 + 3) * 132 + row] = va.w;
        float4 vb = *(const float4*)(Z + (size_t)(bj * 128 + row) * F_Z + kq * 4);
        Bs[(kq * 4 + 0) * 132 + row] = vb.x;
        Bs[(kq * 4 + 1) * 132 + row] = vb.y;
        Bs[(kq * 4 + 2) * 132 + row] = vb.z;
        Bs[(kq * 4 + 3) * 132 + row] = vb.w;
    }
    __syncthreads();

    unsigned long long acc[8][4];
#pragma unroll
    for (int i = 0; i < 8; i++)
#pragma unroll
        for (int j = 0; j < 4; j++) acc[i][j] = 0ull;

#pragma unroll 8
    for (int k = 0; k < 64; k++) {
        const float* ap = As + k * 132 + ty * 8;
        const float* bp = Bs + k * 132 + tx * 8;
        float4 a0 = *(const float4*)(ap);
        float4 a1 = *(const float4*)(ap + 4);
        ulonglong2 b0 = *(const ulonglong2*)(bp);
        ulonglong2 b1 = *(const ulonglong2*)(bp + 4);
        unsigned long long A[8];
        A[0] = pk2(a0.x, a0.x); A[1] = pk2(a0.y, a0.y);
        A[2] = pk2(a0.z, a0.z); A[3] = pk2(a0.w, a0.w);
        A[4] = pk2(a1.x, a1.x); A[5] = pk2(a1.y, a1.y);
        A[6] = pk2(a1.z, a1.z); A[7] = pk2(a1.w, a1.w);
#pragma unroll
        for (int i = 0; i < 8; i++) {
            fma2(acc[i][0], A[i], b0.x);
            fma2(acc[i][1], A[i], b0.y);
            fma2(acc[i][2], A[i], b1.x);
            fma2(acc[i][3], A[i], b1.y);
        }
    }

    float s[8][8];
#pragma unroll
    for (int i = 0; i < 8; i++) {
#pragma unroll
        for (int j = 0; j < 4; j++) {
            float2 p = upk2(acc[i][j]);
            s[i][2 * j]     = sigm(p.x);
            s[i][2 * j + 1] = sigm(p.y);
        }
    }

    const size_t NN = (size_t)NNODES;
    int row0 = bi * 128 + ty * 8, col0 = bj * 128 + tx * 8;
#pragma unroll
    for (int i = 0; i < 8; i++) {
        float* p = out + (size_t)(row0 + i) * NN + col0;
        *(float4*)(p)     = make_float4(s[i][0], s[i][1], s[i][2], s[i][3]);
        *(float4*)(p + 4) = make_float4(s[i][4], s[i][5], s[i][6], s[i][7]);
    }

    if (bi != bj) {
        __syncthreads();                       // done reading As/Bs
        float* Ts = sm;                        // 128 x 129 staging (16512 <= 16896 floats)
#pragma unroll
        for (int i = 0; i < 8; i++)
#pragma unroll
            for (int j = 0; j < 8; j++)
                Ts[(tx * 8 + j) * 129 + (ty * 8 + i)] = s[i][j];
        __syncthreads();
#pragma unroll
        for (int i = 0; i < 8; i++) {
            int rr = bj * 128 + ty * 8 + i;
            const float* src = Ts + (ty * 8 + i) * 129 + tx * 8;
            float* p = out + (size_t)rr * NN + bi * 128 + tx * 8;
            *(float4*)(p)     = make_float4(src[0], src[1], src[2], src[3]);
            *(float4*)(p + 4) = make_float4(src[4], src[5], src[6], src[7]);
        }
    }
}

// ---------------- launch ----------------
extern "C" void kernel_launch(void* const* d_in, const int* in_sizes, int n_in,
                              void* d_out, int out_size) {
    const float* features = (const float*)d_in[0];
    const float* W1 = (const float*)d_in[1];
    const float* b1 = (const float*)d_in[2];
    const float* Wm = (const float*)d_in[3];
    const float* bm = (const float*)d_in[4];
    const float* Ws = (const float*)d_in[5];
    const float* bs = (const float*)d_in[6];
    const float* noise = (const float*)d_in[7];
    const int* es = (const int*)d_in[8];
    const int* ed = (const int*)d_in[9];

    float* out = (float*)d_out;
    float* zb = out + (size_t)NNODES * NNODES;   // z lives at tail of output

    static bool attr_done = false;
    if (!attr_done) {
        cudaFuncSetAttribute(k_biggemm, cudaFuncAttributeMaxDynamicSharedMemorySize,
                             2 * 64 * 132 * (int)sizeof(float));
        attr_done = true;
    }

    k_zero<<<NNODES / 256, 256>>>();
    k_degree<<<NEDGES / 256, 256>>>(es, ed);
    k_scan<<<1, 1024>>>();
    k_fill<<<NEDGES / 256, 256>>>(es, ed);
    k_gemm1<<<NNODES / 64, 256>>>(features, W1);
    k_agg1<<<(NNODES * 32) / 256, 256>>>(b1);
    k_agg2<<<(NNODES * 32) / 256, 256>>>();
    k_gemm2<<<NNODES / 64, 256>>>(Wm, bm, Ws, bs, noise, zb);
    dim3 grid(NNODES / 128, NNODES / 128);
    k_biggemm<<<grid, 256, 2 * 64 * 132 * sizeof(float)>>>(zb, out);
}

// round 16
// speedup vs baseline: 1.4748x; 1.3344x over previous
#include <cuda_runtime.h>
#include <cuda_bf16.h>
#include <cstdint>

#define NNODES 16384
#define NEDGES 262144
#define F_IN   256
#define F_H    128
#define F_Z    64

// ---------------- scratch (static device memory; no allocation) ----------------
__device__ __align__(256) int   g_degi_src[NNODES];
__device__ __align__(256) int   g_degi_dst[NNODES];
__device__ __align__(256) int   g_rowptr[NNODES + 1];
__device__ __align__(256) int   g_cursor[NNODES];
__device__ __align__(256) int   g_eidx[NEDGES];
__device__ __align__(256) float g_cs[NNODES];
__device__ __align__(256) float g_cd[NNODES];
__device__ __align__(256) float g_hpre[NNODES * F_H];   // (x*c_src)@W1
__device__ __align__(256) float g_hs  [NNODES * F_H];   // relu(conv1)*c_src
__device__ __align__(256) float g_agg2[NNODES * F_H];   // CSR-gather of g_hs

// ---------------- helpers ----------------
__device__ __forceinline__ float sigm(float x) {
    return __fdividef(1.0f, 1.0f + __expf(-x));
}

// ---------------- K0: zero small int scratch (re-zeroed every replay) ----------------
__global__ void k_zero() {
    int i = blockIdx.x * blockDim.x + threadIdx.x;   // 16384 threads
    g_degi_src[i] = 0;
    g_degi_dst[i] = 0;
    g_cursor[i] = 0;
}

// ---------------- K1: integer degrees ----------------
__global__ void k_degree(const int* __restrict__ es, const int* __restrict__ ed) {
    int i = blockIdx.x * blockDim.x + threadIdx.x;
    if (i < NEDGES) {
        atomicAdd(&g_degi_src[es[i]], 1);
        atomicAdd(&g_degi_dst[ed[i]], 1);
    }
}

// ---------------- K2: exclusive scan of in-degrees -> rowptr, plus norms ----------------
__global__ __launch_bounds__(1024) void k_scan() {
    __shared__ int sm[1024];
    int tid = threadIdx.x;
    int base = tid * 16;
    int loc[16];
    int run = 0;
#pragma unroll
    for (int j = 0; j < 16; j++) { loc[j] = run; run += g_degi_dst[base + j]; }
    sm[tid] = run;
    __syncthreads();
    for (int off = 1; off < 1024; off <<= 1) {
        int v = (tid >= off) ? sm[tid - off] : 0;
        __syncthreads();
        sm[tid] += v;
        __syncthreads();
    }
    int excl = sm[tid] - run;
#pragma unroll
    for (int j = 0; j < 16; j++) g_rowptr[base + j] = excl + loc[j];
    if (tid == 1023) g_rowptr[NNODES] = excl + run;
#pragma unroll
    for (int j = 0; j < 16; j++) {
        int i = base + j;
        int ds = g_degi_src[i], dd = g_degi_dst[i];
        g_cs[i] = ds > 0 ? rsqrtf((float)ds) : 0.f;
        g_cd[i] = dd > 0 ? rsqrtf((float)dd) : 0.f;
    }
}

// ---------------- K3: CSR fill ----------------
__global__ void k_fill(const int* __restrict__ es, const int* __restrict__ ed) {
    int e = blockIdx.x * blockDim.x + threadIdx.x;
    if (e < NEDGES) {
        int d = ed[e];
        int pos = g_rowptr[d] + atomicAdd(&g_cursor[d], 1);
        g_eidx[pos] = es[e];
    }
}

// ---------------- K4: GEMM1  h_pre = (x * c_src) @ W1 ----------------
__global__ __launch_bounds__(256) void k_gemm1(const float* __restrict__ X, const float* __restrict__ W1) {
    __shared__ float As[32 * 68];
    __shared__ float Bs[32 * 128];
    int tid = threadIdx.x;
    int tx = tid & 15, ty = tid >> 4;
    int row0 = blockIdx.x * 64;

    float acc[4][8];
#pragma unroll
    for (int i = 0; i < 4; i++)
#pragma unroll
        for (int j = 0; j < 8; j++) acc[i][j] = 0.f;

    for (int k0 = 0; k0 < F_IN; k0 += 32) {
#pragma unroll
        for (int r = 0; r < 2; r++) {
            int idx = tid + 256 * r;
            int row = idx >> 3, kq = idx & 7;
            float c = g_cs[row0 + row];
            float4 v = *(const float4*)(X + (size_t)(row0 + row) * F_IN + k0 + kq * 4);
            As[(kq * 4 + 0) * 68 + row] = v.x * c;
            As[(kq * 4 + 1) * 68 + row] = v.y * c;
            As[(kq * 4 + 2) * 68 + row] = v.z * c;
            As[(kq * 4 + 3) * 68 + row] = v.w * c;
        }
#pragma unroll
        for (int r = 0; r < 4; r++) {
            int idx = tid + 256 * r;
            int kk = idx >> 5, jq = idx & 31;
            *(float4*)(Bs + kk * 128 + jq * 4) =
                *(const float4*)(W1 + (size_t)(k0 + kk) * F_H + jq * 4);
        }
        __syncthreads();
#pragma unroll 8
        for (int k = 0; k < 32; k++) {
            float4 a = *(const float4*)(As + k * 68 + ty * 4);
            float4 b0 = *(const float4*)(Bs + k * 128 + tx * 8);
            float4 b1 = *(const float4*)(Bs + k * 128 + tx * 8 + 4);
            float av[4] = {a.x, a.y, a.z, a.w};
            float bv[8] = {b0.x, b0.y, b0.z, b0.w, b1.x, b1.y, b1.z, b1.w};
#pragma unroll
            for (int i = 0; i < 4; i++)
#pragma unroll
                for (int j = 0; j < 8; j++) acc[i][j] = fmaf(av[i], bv[j], acc[i][j]);
        }
        __syncthreads();
    }
#pragma unroll
    for (int i = 0; i < 4; i++) {
        float* p = g_hpre + (size_t)(row0 + ty * 4 + i) * F_H + tx * 8;
        *(float4*)(p)     = make_float4(acc[i][0], acc[i][1], acc[i][2], acc[i][3]);
        *(float4*)(p + 4) = make_float4(acc[i][4], acc[i][5], acc[i][6], acc[i][7]);
    }
}

// ---------------- K5/K6: CSR gather-aggregate, one warp per dst node ----------------
__global__ __launch_bounds__(256) void k_agg1(const float* __restrict__ b1) {
    int gid = blockIdx.x * blockDim.x + threadIdx.x;
    int node = gid >> 5;
    int lane = gid & 31;
    int beg = g_rowptr[node], end = g_rowptr[node + 1];
    float4 a0 = make_float4(0, 0, 0, 0), a1 = make_float4(0, 0, 0, 0);
    int i = beg;
    for (; i + 2 <= end; i += 2) {
        int s0 = __ldg(g_eidx + i), s1 = __ldg(g_eidx + i + 1);
        float4 v0 = *(const float4*)(g_hpre + (size_t)s0 * F_H + lane * 4);
        float4 v1 = *(const float4*)(g_hpre + (size_t)s1 * F_H + lane * 4);
        a0.x += v0.x; a0.y += v0.y; a0.z += v0.z; a0.w += v0.w;
        a1.x += v1.x; a1.y += v1.y; a1.z += v1.z; a1.w += v1.w;
    }
    if (i < end) {
        int s0 = __ldg(g_eidx + i);
        float4 v0 = *(const float4*)(g_hpre + (size_t)s0 * F_H + lane * 4);
        a0.x += v0.x; a0.y += v0.y; a0.z += v0.z; a0.w += v0.w;
    }
    float cd = g_cd[node], cs = g_cs[node];
    float4 b = *(const float4*)(b1 + lane * 4);
    float4 h;
    h.x = fmaxf(fmaf(a0.x + a1.x, cd, b.x), 0.f) * cs;
    h.y = fmaxf(fmaf(a0.y + a1.y, cd, b.y), 0.f) * cs;
    h.z = fmaxf(fmaf(a0.z + a1.z, cd, b.z), 0.f) * cs;
    h.w = fmaxf(fmaf(a0.w + a1.w, cd, b.w), 0.f) * cs;
    *(float4*)(g_hs + (size_t)node * F_H + lane * 4) = h;
}

__global__ __launch_bounds__(256) void k_agg2() {
    int gid = blockIdx.x * blockDim.x + threadIdx.x;
    int node = gid >> 5;
    int lane = gid & 31;
    int beg = g_rowptr[node], end = g_rowptr[node + 1];
    float4 a0 = make_float4(0, 0, 0, 0), a1 = make_float4(0, 0, 0, 0);
    int i = beg;
    for (; i + 2 <= end; i += 2) {
        int s0 = __ldg(g_eidx + i), s1 = __ldg(g_eidx + i + 1);
        float4 v0 = *(const float4*)(g_hs + (size_t)s0 * F_H + lane * 4);
        float4 v1 = *(const float4*)(g_hs + (size_t)s1 * F_H + lane * 4);
        a0.x += v0.x; a0.y += v0.y; a0.z += v0.z; a0.w += v0.w;
        a1.x += v1.x; a1.y += v1.y; a1.z += v1.z; a1.w += v1.w;
    }
    if (i < end) {
        int s0 = __ldg(g_eidx + i);
        float4 v0 = *(const float4*)(g_hs + (size_t)s0 * F_H + lane * 4);
        a0.x += v0.x; a0.y += v0.y; a0.z += v0.z; a0.w += v0.w;
    }
    float4 r;
    r.x = a0.x + a1.x; r.y = a0.y + a1.y; r.z = a0.z + a1.z; r.w = a0.w + a1.w;
    *(float4*)(g_agg2 + (size_t)node * F_H + lane * 4) = r;
}

// ---------------- K7: fused GEMM2  mean/log_std -> z ----------------
__global__ __launch_bounds__(256) void k_gemm2(const float* __restrict__ Wm, const float* __restrict__ bm,
                                               const float* __restrict__ Ws, const float* __restrict__ bs,
                                               const float* __restrict__ noise, float* __restrict__ zb) {
    __shared__ float As[32 * 68];
    __shared__ float Bm[32 * 64];
    __shared__ float Bv[32 * 64];
    int tid = threadIdx.x;
    int tx = tid & 15, ty = tid >> 4;
    int row0 = blockIdx.x * 64;

    float am[4][4], av[4][4];
#pragma unroll
    for (int i = 0; i < 4; i++)
#pragma unroll
        for (int j = 0; j < 4; j++) { am[i][j] = 0.f; av[i][j] = 0.f; }

    for (int k0 = 0; k0 < F_H; k0 += 32) {
#pragma unroll
        for (int r = 0; r < 2; r++) {
            int idx = tid + 256 * r;
            int row = idx >> 3, kq = idx & 7;
            float4 v = *(const float4*)(g_agg2 + (size_t)(row0 + row) * F_H + k0 + kq * 4);
            As[(kq * 4 + 0) * 68 + row] = v.x;
            As[(kq * 4 + 1) * 68 + row] = v.y;
            As[(kq * 4 + 2) * 68 + row] = v.z;
            As[(kq * 4 + 3) * 68 + row] = v.w;
        }
#pragma unroll
        for (int r = 0; r < 2; r++) {
            int idx = tid + 256 * r;
            int kk = idx >> 4;
            int jq = idx & 15;
            *(float4*)(Bm + kk * 64 + jq * 4) =
                *(const float4*)(Wm + (size_t)(k0 + kk) * F_Z + jq * 4);
            *(float4*)(Bv + kk * 64 + jq * 4) =
                *(const float4*)(Ws + (size_t)(k0 + kk) * F_Z + jq * 4);
        }
        __syncthreads();
#pragma unroll 8
        for (int k = 0; k < 32; k++) {
            float4 a = *(const float4*)(As + k * 68 + ty * 4);
            float4 m4 = *(const float4*)(Bm + k * 64 + tx * 4);
            float4 v4 = *(const float4*)(Bv + k * 64 + tx * 4);
            float avv[4] = {a.x, a.y, a.z, a.w};
            float mv[4] = {m4.x, m4.y, m4.z, m4.w};
            float vv[4] = {v4.x, v4.y, v4.z, v4.w};
#pragma unroll
            for (int i = 0; i < 4; i++)
#pragma unroll
                for (int j = 0; j < 4; j++) {
                    am[i][j] = fmaf(avv[i], mv[j], am[i][j]);
                    av[i][j] = fmaf(avv[i], vv[j], av[i][j]);
                }
        }
        __syncthreads();
    }
    float4 bmv = *(const float4*)(bm + tx * 4);
    float4 bsv = *(const float4*)(bs + tx * 4);
#pragma unroll
    for (int i = 0; i < 4; i++) {
        int node = row0 + ty * 4 + i;
        float cd = g_cd[node];
        float4 nz = *(const float4*)(noise + (size_t)node * F_Z + tx * 4);
        float4 z;
        z.x = fmaf(am[i][0], cd, bmv.x) + nz.x * __expf(fmaf(av[i][0], cd, bsv.x));
        z.y = fmaf(am[i][1], cd, bmv.y) + nz.y * __expf(fmaf(av[i][1], cd, bsv.y));
        z.z = fmaf(am[i][2], cd, bmv.z) + nz.z * __expf(fmaf(av[i][2], cd, bsv.z));
        z.w = fmaf(am[i][3], cd, bmv.w) + nz.w * __expf(fmaf(av[i][3], cd, bsv.w));
        *(float4*)(zb + (size_t)node * F_Z + tx * 4) = z;
    }
}

// ---------------- K8: decoder pre = sigmoid(Z Z^T) via mma.sync bf16, 2-term split ----
// Baseline-PTX tensor path (no tcgen05 / no 'a' features — harness targets sm_103).
// A rows: [hi | lo | hi], B rows: [hi | hi | lo]  (K = 192 bf16; only lo*lo dropped)
// 128x128 tile/CTA, 8 warps x (32x64) sub-tiles, m16n8k16 fragments, 12 k-steps.
// NOTE: all 'staged' accesses are SCALAR — stride 129 is odd, so any
// vectorized (float2/float4) access at row*129+... is misaligned (R13 fault).
#define SA 200                                // bf16 row stride (conflict-free frag LDS)
#define DEC_SMEM (2 * 128 * SA * 2)           // 102400 B: A tile + B tile

__device__ __forceinline__ void mma16816(float* c, const uint32_t a[4],
                                         uint32_t b0, uint32_t b1) {
    asm volatile(
        "mma.sync.aligned.m16n8k16.row.col.f32.bf16.bf16.f32 "
        "{%0,%1,%2,%3}, {%4,%5,%6,%7}, {%8,%9}, {%0,%1,%2,%3};"
        : "+f"(c[0]), "+f"(c[1]), "+f"(c[2]), "+f"(c[3])
        : "r"(a[0]), "r"(a[1]), "r"(a[2]), "r"(a[3]), "r"(b0), "r"(b1));
}

__global__ __launch_bounds__(256, 2) void k_decoder(const float* __restrict__ Z,
                                                    float* __restrict__ out) {
    int bi = blockIdx.y, bj = blockIdx.x;
    if (bj < bi) return;
    extern __shared__ char smraw[];
    __nv_bfloat16* As = (__nv_bfloat16*)smraw;           // [128][SA]
    __nv_bfloat16* Bs = As + 128 * SA;                   // [128][SA]
    int tid = threadIdx.x, wid = tid >> 5, lane = tid & 31;
    int g = lane >> 2, c4 = lane & 3;

    // ---- build bf16 split tiles: threads 0-127 -> A (rows of bi), 128-255 -> B (bj)
    {
        int half = tid >> 7;
        int row = tid & 127;
        int gr = (half ? bj : bi) * 128 + row;
        const float* zr = Z + (size_t)gr * F_Z;
        uint32_t* trow = (uint32_t*)((half ? Bs : As) + row * SA);
        uint32_t hp[32], lp[32];
#pragma unroll
        for (int p = 0; p < 16; p++) {
            float4 v = *(const float4*)(zr + p * 4);
            __nv_bfloat162 h01 = __floats2bfloat162_rn(v.x, v.y);
            __nv_bfloat162 h23 = __floats2bfloat162_rn(v.z, v.w);
            hp[2 * p]     = *(uint32_t*)&h01;
            hp[2 * p + 1] = *(uint32_t*)&h23;
            __nv_bfloat162 l01 = __floats2bfloat162_rn(v.x - __low2float(h01), v.y - __high2float(h01));
            __nv_bfloat162 l23 = __floats2bfloat162_rn(v.z - __low2float(h23), v.w - __high2float(h23));
            lp[2 * p]     = *(uint32_t*)&l01;
            lp[2 * p + 1] = *(uint32_t*)&l23;
        }
#pragma unroll
        for (int p = 0; p < 32; p++) {
            trow[p]      = hp[p];                     // seg0 (cols 0..63):   hi | hi
            trow[32 + p] = half ? hp[p] : lp[p];      // seg1 (cols 64..127): A lo, B hi
            trow[64 + p] = half ? lp[p] : hp[p];      // seg2 (cols 128..191):A hi, B lo
        }
    }
    __syncthreads();

    // ---- warp sub-tile: rows m0..m0+31, cols n0..n0+63
    int m0 = (wid & 3) * 32, n0 = (wid >> 2) * 64;
    float acc[2][8][4];
#pragma unroll
    for (int mi = 0; mi < 2; mi++)
#pragma unroll
        for (int ni = 0; ni < 8; ni++)
#pragma unroll
            for (int q = 0; q < 4; q++) acc[mi][ni][q] = 0.f;

#pragma unroll
    for (int ks = 0; ks < 12; ks++) {
        int k0 = ks * 16;
        uint32_t a[2][4];
#pragma unroll
        for (int mi = 0; mi < 2; mi++) {
            const __nv_bfloat16* pa = As + (m0 + mi * 16 + g) * SA + k0 + 2 * c4;
            a[mi][0] = *(const uint32_t*)pa;               // row g,   k 2c..2c+1
            a[mi][1] = *(const uint32_t*)(pa + 8 * SA);    // row g+8, k 2c..2c+1
            a[mi][2] = *(const uint32_t*)(pa + 8);         // row g,   k 2c+8..+9
            a[mi][3] = *(const uint32_t*)(pa + 8 * SA + 8);// row g+8, k 2c+8..+9
        }
#pragma unroll
        for (int ni = 0; ni < 8; ni++) {
            const __nv_bfloat16* pb = Bs + (n0 + ni * 8 + g) * SA + k0 + 2 * c4;
            uint32_t b0 = *(const uint32_t*)pb;            // n g, k 2c..2c+1
            uint32_t b1 = *(const uint32_t*)(pb + 8);      // n g, k 2c+8..+9
            mma16816(acc[0][ni], a[0], b0, b1);
            mma16816(acc[1][ni], a[1], b0, b1);
        }
    }

    // ---- epilogue: sigmoid -> staged smem (stride 129, SCALAR stores) ----
    __syncthreads();                           // all warps done reading As/Bs
    float* staged = (float*)smraw;             // 128 x 129 f32 = 66048 B <= DEC_SMEM
#pragma unroll
    for (int mi = 0; mi < 2; mi++)
#pragma unroll
        for (int ni = 0; ni < 8; ni++) {
            int r0 = m0 + mi * 16 + g;
            int col = n0 + ni * 8 + 2 * c4;
            staged[r0 * 129 + col]           = sigm(acc[mi][ni][0]);
            staged[r0 * 129 + col + 1]       = sigm(acc[mi][ni][1]);
            staged[(r0 + 8) * 129 + col]     = sigm(acc[mi][ni][2]);
            staged[(r0 + 8) * 129 + col + 1] = sigm(acc[mi][ni][3]);
        }
    __syncthreads();

    // ---- coalesced GMEM stores: direct tile (scalar LDS -> float4 STG) + mirror
    const size_t NN = (size_t)NNODES;
#pragma unroll
    for (int rr = 0; rr < 16; rr++) {
        int row = wid * 16 + rr;
        const float* srow = staged + row * 129 + lane * 4;
        float4 v = make_float4(srow[0], srow[1], srow[2], srow[3]);
        *(float4*)(out + (size_t)(bi * 128 + row) * NN + bj * 128 + lane * 4) = v;
    }
    if (bi != bj) {
#pragma unroll
        for (int rr = 0; rr < 16; rr++) {
            int row = wid * 16 + rr;          // mirror row == staged column
#pragma unroll
            for (int j = 0; j < 4; j++) {
                int c = lane + 32 * j;        // stride-1 lanes -> conflict-free LDS, coalesced STG
                out[(size_t)(bj * 128 + row) * NN + bi * 128 + c] = staged[c * 129 + row];
            }
        }
    }
}

// ---------------- launch ----------------
extern "C" void kernel_launch(void* const* d_in, const int* in_sizes, int n_in,
                              void* d_out, int out_size) {
    const float* features = (const float*)d_in[0];
    const float* W1 = (const float*)d_in[1];
    const float* b1 = (const float*)d_in[2];
    const float* Wm = (const float*)d_in[3];
    const float* bm = (const float*)d_in[4];
    const float* Ws = (const float*)d_in[5];
    const float* bs = (const float*)d_in[6];
    const float* noise = (const float*)d_in[7];
    const int* es = (const int*)d_in[8];
    const int* ed = (const int*)d_in[9];

    float* out = (float*)d_out;
    float* zb = out + (size_t)NNODES * NNODES;   // z lives at tail of output

    static bool attr_done = false;
    if (!attr_done) {
        cudaFuncSetAttribute(k_decoder, cudaFuncAttributeMaxDynamicSharedMemorySize, DEC_SMEM);
        attr_done = true;
    }

    k_zero<<<NNODES / 256, 256>>>();
    k_degree<<<NEDGES / 256, 256>>>(es, ed);
    k_scan<<<1, 1024>>>();
    k_fill<<<NEDGES / 256, 256>>>(es, ed);
    k_gemm1<<<NNODES / 64, 256>>>(features, W1);
    k_agg1<<<(NNODES * 32) / 256, 256>>>(b1);
    k_agg2<<<(NNODES * 32) / 256, 256>>>();
    k_gemm2<<<NNODES / 64, 256>>>(Wm, bm, Ws, bs, noise, zb);
    dim3 grid(NNODES / 128, NNODES / 128);
    k_decoder<<<grid, 256, DEC_SMEM>>>(zb, out);
}